// round 15
// baseline (speedup 1.0000x reference)
#include <cuda_runtime.h>
#include <cuda_bf16.h>
#include <cuda_fp16.h>
#include <math.h>
#include <stdint.h>

// ---------------- constants ----------------
#define BATCH 4
#define SEQ   2048
#define EMB   2048
#define NHEAD 16
#define HDIM  128
#define MROWS (BATCH*SEQ)               // 8192
#define ELEMS ((size_t)BATCH*SEQ*EMB)   // 16777216
#define RMS_EPS 1.1920929e-07f
// softmax: exp(s*scale) = exp2(s * SL2E), SL2E = (1/sqrt(128))*log2(e)
#define SL2E 0.1275290959651556f
#define WSCALE 64.0f
#define WINV   0.015625f

// ---------------- scratch (device globals: allocation-free) ----------------
__device__ __half g_a[ELEMS];                      // fp16 A operand (x, then Y)
__device__ __half g_wthi[(size_t)4*EMB*EMB];       // transposed weights (x64) hi
__device__ __half g_wtlo[(size_t)4*EMB*EMB];       // lo
__device__ __half g_qh[ELEMS];
__device__ __half g_ql[ELEMS];
__device__ __half g_kh[ELEMS];                     // K single fp16
__device__ __half g_vh[ELEMS];                     // V single fp16
__device__ float g_cos[SEQ*64];
__device__ float g_sin[SEQ*64];

// =====================================================================
// PTX helpers (standard sm_80+ instructions; valid on plain sm_103)
// =====================================================================
__device__ __forceinline__ uint32_t smem_to_u32(const void* p) {
    uint32_t a;
    asm("{ .reg .u64 t; cvta.to.shared.u64 t, %1; cvt.u32.u64 %0, t; }"
        : "=r"(a) : "l"(p));
    return a;
}

__device__ __forceinline__ void ldsm4(uint32_t* r, uint32_t addr) {
    asm volatile("ldmatrix.sync.aligned.m8n8.x4.shared.b16 {%0,%1,%2,%3}, [%4];"
        : "=r"(r[0]), "=r"(r[1]), "=r"(r[2]), "=r"(r[3]) : "r"(addr));
}
__device__ __forceinline__ void ldsm4t(uint32_t* r, uint32_t addr) {
    asm volatile("ldmatrix.sync.aligned.m8n8.x4.trans.shared.b16 {%0,%1,%2,%3}, [%4];"
        : "=r"(r[0]), "=r"(r[1]), "=r"(r[2]), "=r"(r[3]) : "r"(addr));
}

__device__ __forceinline__ void mma_f16(float* c, const uint32_t* a, const uint32_t* b) {
    asm volatile(
        "mma.sync.aligned.m16n8k16.row.col.f32.f16.f16.f32 "
        "{%0,%1,%2,%3}, {%4,%5,%6,%7}, {%8,%9}, {%0,%1,%2,%3};"
        : "+f"(c[0]), "+f"(c[1]), "+f"(c[2]), "+f"(c[3])
        : "r"(a[0]), "r"(a[1]), "r"(a[2]), "r"(a[3]), "r"(b[0]), "r"(b[1]));
}

__device__ __forceinline__ uint32_t pack_f16x2(float lo, float hi) {
    __half2 h = __floats2half2_rn(lo, hi);
    return *(uint32_t*)&h;
}

// fast exp2 (single SASS MUFU.EX2)
__device__ __forceinline__ float ex2(float x) {
    float y;
    asm("ex2.approx.f32 %0, %1;" : "=f"(y) : "f"(x));
    return y;
}

#define CP_ASYNC16(dst, src) \
    asm volatile("cp.async.cg.shared.global [%0], [%1], 16;" :: "r"(dst), "l"(src) : "memory")
#define CP_COMMIT() asm volatile("cp.async.commit_group;" ::: "memory")
#define CP_WAIT0()  asm volatile("cp.async.wait_group 0;" ::: "memory")

// =====================================================================
// conv16: fp32 -> fp16 (single)
// =====================================================================
__global__ __launch_bounds__(256) void conv16_kernel(
    const float* __restrict__ in, __half* __restrict__ out, int n4)
{
    int i = blockIdx.x * 256 + threadIdx.x;
    if (i >= n4) return;
    float4 v = ((const float4*)in)[i];
    uint2 o;
    o.x = pack_f16x2(v.x, v.y);
    o.y = pack_f16x2(v.z, v.w);
    ((uint2*)out)[i] = o;
}

// =====================================================================
// 4 weights: transpose + x64 scale + fp16 hi/lo split
// =====================================================================
__global__ __launch_bounds__(256) void wsplit4_kernel(
    const float* __restrict__ w0, const float* __restrict__ w1,
    const float* __restrict__ w2, const float* __restrict__ w3,
    __half* __restrict__ hi_base, __half* __restrict__ lo_base)
{
    __shared__ float tile[32][33];
    const int z = blockIdx.z;
    const float* w = (z == 0) ? w0 : (z == 1) ? w1 : (z == 2) ? w2 : w3;
    __half* hi = hi_base + (size_t)z * EMB * EMB;
    __half* lo = lo_base + (size_t)z * EMB * EMB;

    int n0 = blockIdx.x * 32, k0 = blockIdx.y * 32;
    int tx = threadIdx.x & 31, ty = threadIdx.x >> 5;
#pragma unroll
    for (int i = 0; i < 32; i += 8)
        tile[ty + i][tx] = w[(size_t)(k0 + ty + i) * EMB + n0 + tx];
    __syncthreads();
#pragma unroll
    for (int i = 0; i < 32; i += 8) {
        float v = tile[tx][ty + i] * WSCALE;
        __half h = __float2half_rn(v);
        size_t o = (size_t)(n0 + ty + i) * EMB + k0 + tx;
        hi[o] = h;
        lo[o] = __float2half_rn(v - __half2float(h));
    }
}

// =====================================================================
// RoPE table precompute (double precision, once)
// =====================================================================
__global__ __launch_bounds__(256) void rope_table_kernel(
    float* __restrict__ ct, float* __restrict__ st)
{
    const int idx = blockIdx.x * 256 + threadIdx.x;
    if (idx >= SEQ * 64) return;
    const int tp = idx >> 6, i = idx & 63;
    double inv = exp(-((double)i / 64.0) * log(10000.0));
    double ang = (double)tp * inv;
    double sd, cd;
    sincos(ang, &sd, &cd);
    ct[idx] = (float)cd;
    st[idx] = (float)sd;
}

// =====================================================================
// Shared GEMM tile config (both GEMM kernels)
// Block tile 128x256x64, 8 warps (2 x 4), warp tile 64x64.
// A single fp16; B fp16 hi/lo (x64). 2 chains. 2-stage cp.async, 1 sync/iter.
// =====================================================================
#define BM 128
#define BN 256
#define BK 64
#define RSTRB 144
#define TA (128 * RSTRB)          // 18432 (A: one tile)
#define TB (256 * RSTRB)          // 36864
#define STG_B (TA + 2*TB)         // 92160
#define GEMM_SMEM (2 * STG_B)     // 184320
#define CSTR 257                  // fp32 epilogue staging stride

// mainloop as a macro-expanded inline (shared between the two kernels)
#define GEMM_MAINLOOP(A_, Bhi_, Blo_, K_)                                      \
    float acc[4][8][4];                                                        \
    _Pragma("unroll")                                                          \
    for (int i = 0; i < 4; i++)                                                \
        _Pragma("unroll")                                                      \
        for (int j = 0; j < 8; j++)                                            \
            _Pragma("unroll")                                                  \
            for (int r = 0; r < 4; r++) acc[i][j][r] = 0.f;                    \
    auto load_stage = [&](int s, int k0) {                                     \
        const uint32_t base = sb + s * STG_B;                                  \
        _Pragma("unroll")                                                      \
        for (int i = 0; i < 4; i++) {                                          \
            const int idx = t + i * 256;                                       \
            const int r = idx >> 3, c = idx & 7;                               \
            CP_ASYNC16(base + r * RSTRB + c * 16,                              \
                       A_ + (size_t)(row0 + r) * K_ + k0 + c * 8);             \
        }                                                                      \
        _Pragma("unroll")                                                      \
        for (int i = 0; i < 8; i++) {                                          \
            const int idx = t + i * 256;                                       \
            const int r = idx >> 3, c = idx & 7;                               \
            const size_t g = (size_t)(col0 + r) * K_ + k0 + c * 8;             \
            const uint32_t d = base + TA + r * RSTRB + c * 16;                 \
            CP_ASYNC16(d, Bhi_ + g);                                           \
            CP_ASYNC16(d + TB, Blo_ + g);                                      \
        }                                                                      \
    };                                                                         \
    const int nIter = K_ / BK;                                                 \
    load_stage(0, 0);                                                          \
    CP_COMMIT();                                                               \
    for (int it = 0; it < nIter; it++) {                                       \
        CP_WAIT0();                                                            \
        __syncthreads();                                                       \
        if (it + 1 < nIter) {                                                  \
            load_stage((it + 1) & 1, (it + 1) * BK);                           \
            CP_COMMIT();                                                       \
        }                                                                      \
        const uint32_t abase = sb + (it & 1) * STG_B;                          \
        const uint32_t bbase = abase + TA;                                     \
        const int arow = warp_m * 64 + (lane & 15);                            \
        const int brow = warp_n * 64 + ((lane >> 4) << 3) + (lane & 7);        \
        _Pragma("unroll")                                                      \
        for (int ks = 0; ks < 4; ks++) {                                       \
            uint32_t ah[4][4], bh[4][4], bl[4][4];                             \
            const uint32_t acol = ks * 32 + ((lane >> 4) << 4);                \
            const uint32_t bcol = ks * 32 + (((lane >> 3) & 1) << 4);          \
            _Pragma("unroll")                                                  \
            for (int mf = 0; mf < 4; mf++)                                     \
                ldsm4(ah[mf], abase + (arow + mf * 16) * RSTRB + acol);        \
            _Pragma("unroll")                                                  \
            for (int bf = 0; bf < 4; bf++) {                                   \
                const uint32_t bd = bbase + (brow + bf * 16) * RSTRB + bcol;   \
                ldsm4(bh[bf], bd);                                             \
                ldsm4(bl[bf], bd + TB);                                        \
            }                                                                  \
            _Pragma("unroll")                                                  \
            for (int mf = 0; mf < 4; mf++) {                                   \
                _Pragma("unroll")                                              \
                for (int nf = 0; nf < 8; nf++) {                               \
                    const uint32_t* bhp = &bh[nf >> 1][(nf & 1) * 2];          \
                    const uint32_t* blp = &bl[nf >> 1][(nf & 1) * 2];          \
                    mma_f16(acc[mf][nf], ah[mf], bhp);                         \
                    mma_f16(acc[mf][nf], ah[mf], blp);                         \
                }                                                              \
            }                                                                  \
        }                                                                      \
    }

// =====================================================================
// QKV GEMM: N=6144.  Q/K CTAs: fused RoPE+RMSNorm epilogue
// (Q -> fp16 hi/lo, K -> fp16 single).  V CTAs: fp16 single store.
// =====================================================================
__global__ __launch_bounds__(256) void mma_gemm_qkv_kernel(
    const __half* __restrict__ A,
    const __half* __restrict__ Bhi, const __half* __restrict__ Blo,
    __half* __restrict__ qh, __half* __restrict__ ql,
    __half* __restrict__ kh, __half* __restrict__ vh,
    const float* __restrict__ ct, const float* __restrict__ st)
{
    extern __shared__ char smc[];
    const uint32_t sb = smem_to_u32(smc);
    const int t = threadIdx.x;
    const int lane = t & 31;
    const int wid = t >> 5;
    const int warp_m = wid & 1;
    const int warp_n = wid >> 1;
    const int row0 = blockIdx.y * BM;
    const int col0 = blockIdx.x * BN;

    GEMM_MAINLOOP(A, Bhi, Blo, EMB)

    const int rloc = warp_m * 64 + (lane >> 2);
    const int nloc = warp_n * 64 + (lane & 3) * 2;
    const int which = col0 >> 11;   // 0=Q 1=K 2=V

    if (which == 2) {
        // V: direct fp16 single (unscale)
#pragma unroll
        for (int mf = 0; mf < 4; mf++) {
#pragma unroll
            for (int nf = 0; nf < 8; nf++) {
                const float* a = acc[mf][nf];
                const size_t o0 = (size_t)(row0 + rloc + mf * 16) * EMB
                                  + (col0 & 2047) + nloc + nf * 8;
                *(uint32_t*)(vh + o0) = pack_f16x2(a[0] * WINV, a[1] * WINV);
                *(uint32_t*)(vh + o0 + 8 * EMB) = pack_f16x2(a[2] * WINV, a[3] * WINV);
            }
        }
        return;
    }

    // ---- Q/K: stage fp32 to smem, then RoPE + RMSNorm + fp16 write ----
    float* Cs = (float*)smc;   // 128 x 257 fp32 = 131584 B (< GEMM_SMEM)
    __syncthreads();           // mainloop smem reads done before overwrite
#pragma unroll
    for (int mf = 0; mf < 4; mf++) {
#pragma unroll
        for (int nf = 0; nf < 8; nf++) {
            const float* a = acc[mf][nf];
            float* p0 = Cs + (rloc + mf * 16) * CSTR + nloc + nf * 8;
            p0[0] = a[0] * WINV; p0[1] = a[1] * WINV;
            p0[8 * CSTR] = a[2] * WINV; p0[8 * CSTR + 1] = a[3] * WINV;
        }
    }
    __syncthreads();

    {
        const int r  = t & 127;
        const int hh = t >> 7;          // 0 or 1 (two heads per tile)
        float* row = Cs + r * CSTR + hh * 128;
        const int tp = (row0 + r) & (SEQ - 1);
        const float* ctr = ct + tp * 64;
        const float* str = st + tp * 64;

        float sq = 0.f;
#pragma unroll 8
        for (int i = 0; i < 64; i++) {
            const float x1 = row[i], x2 = row[64 + i];
            const float c = ctr[i], s = str[i];
            const float n1 = x1 * c - x2 * s;
            const float n2 = x1 * s + x2 * c;
            sq += n1 * n1 + n2 * n2;
            row[i] = n1;
            row[64 + i] = n2;
        }
        const float rs = rsqrtf(sq * (1.0f / 128.0f) + RMS_EPS);
        const size_t base = (size_t)(row0 + r) * EMB + (col0 & 2047) + hh * 128;

        if (which == 0) {
#pragma unroll 8
            for (int j = 0; j < 64; j++) {
                const float y0 = row[2 * j] * rs;
                const float y1 = row[2 * j + 1] * rs;
                const uint32_t hp = pack_f16x2(y0, y1);
                const __half2 hv = *(__half2*)&hp;
                const uint32_t lp = pack_f16x2(y0 - __half2float(__low2half(hv)),
                                               y1 - __half2float(__high2half(hv)));
                *(uint32_t*)(qh + base + 2 * j) = hp;
                *(uint32_t*)(ql + base + 2 * j) = lp;
            }
        } else {
#pragma unroll 8
            for (int j = 0; j < 64; j++) {
                *(uint32_t*)(kh + base + 2 * j) =
                    pack_f16x2(row[2 * j] * rs, row[2 * j + 1] * rs);
            }
        }
    }
}

// =====================================================================
// Output GEMM: plain fp32 epilogue (kept as its own kernel: low regs)
// =====================================================================
__global__ __launch_bounds__(256) void mma_gemm_out_kernel(
    const __half* __restrict__ A,
    const __half* __restrict__ Bhi, const __half* __restrict__ Blo,
    float* __restrict__ c0)
{
    extern __shared__ char smc[];
    const uint32_t sb = smem_to_u32(smc);
    const int t = threadIdx.x;
    const int lane = t & 31;
    const int wid = t >> 5;
    const int warp_m = wid & 1;
    const int warp_n = wid >> 1;
    const int row0 = blockIdx.y * BM;
    const int col0 = blockIdx.x * BN;

    GEMM_MAINLOOP(A, Bhi, Blo, EMB)

    const int mbase = row0 + warp_m * 64 + (lane >> 2);
    const int nb = col0 + warp_n * 64 + (lane & 3) * 2;
#pragma unroll
    for (int mf = 0; mf < 4; mf++) {
#pragma unroll
        for (int nf = 0; nf < 8; nf++) {
            const float* a = acc[mf][nf];
            const size_t o0 = (size_t)(mbase + mf * 16) * EMB + nb + nf * 8;
            *(float2*)(c0 + o0) = make_float2(a[0] * WINV, a[1] * WINV);
            *(float2*)(c0 + o0 + 8 * EMB) = make_float2(a[2] * WINV, a[3] * WINV);
        }
    }
}

// =====================================================================
// Flash attention (unchanged from R14): S = 2 chains, P·V = 1 chain.
// =====================================================================
#define FL_STR  136
#define FL_ROWB (FL_STR*2)
#define FL_TILE (64*FL_ROWB)            // 17408
#define FL_STG  (2*FL_TILE)             // 34816
#define FL_QLO  (128*FL_ROWB)           // 34816
#define FL_KV0  (4*FL_TILE)             // 69632
#define FL_SMEM (4*FL_TILE + 2*FL_STG)  // 139264

__global__ __launch_bounds__(256, 1) void flash_mma_kernel(
    const __half* __restrict__ Qh, const __half* __restrict__ Ql,
    const __half* __restrict__ Kh, const __half* __restrict__ Vh,
    __half* __restrict__ Y)
{
    extern __shared__ char smc[];
    const uint32_t sb = smem_to_u32(smc);
    const int t = threadIdx.x;
    const int lane = t & 31;
    const int w = t >> 5;
    const int qi = gridDim.x - 1 - blockIdx.x;
    const int h = blockIdx.y, b = blockIdx.z;
    const int qs = qi * 128;
    const size_t hb = ((size_t)b * SEQ) * EMB + (size_t)h * HDIM;

#pragma unroll
    for (int i = 0; i < 8; i++) {
        const int idx = t + i * 256;
        const int r = idx >> 4, c = idx & 15;
        const size_t g = hb + (size_t)(qs + r) * EMB + c * 8;
        CP_ASYNC16(sb + r * FL_ROWB + c * 16, Qh + g);
        CP_ASYNC16(sb + FL_QLO + r * FL_ROWB + c * 16, Ql + g);
    }
    CP_COMMIT();

    auto load_kv = [&](int s, int ks) {
        const uint32_t base = sb + FL_KV0 + s * FL_STG;
#pragma unroll
        for (int i = 0; i < 4; i++) {
            const int idx = t + i * 256;
            const int r = idx >> 4, c = idx & 15;
            const size_t g = hb + (size_t)(ks + r) * EMB + c * 8;
            CP_ASYNC16(base + r * FL_ROWB + c * 16, Kh + g);
            CP_ASYNC16(base + FL_TILE + r * FL_ROWB + c * 16, Vh + g);
        }
    };

    load_kv(0, 0);
    CP_COMMIT();

    float m0 = -INFINITY, m1 = -INFINITY, l0 = 0.f, l1 = 0.f;
    float o[16][4];
#pragma unroll
    for (int i = 0; i < 16; i++)
#pragma unroll
        for (int j = 0; j < 4; j++) o[i][j] = 0.f;

    const uint32_t q_addr = sb + (w * 16 + (lane & 15)) * FL_ROWB + (lane >> 4) * 16;
    const int krow = (lane & 7) + ((lane >> 4) << 3);
    const uint32_t kcolb = ((lane >> 3) & 1) * 16;
    const int vrow = (lane & 7) + (((lane >> 3) & 1) << 3);
    const uint32_t vcolb = (lane >> 4) * 16;

    const int r0g = qs + w * 16 + (lane >> 2);
    const int r1g = r0g + 8;
    const int nkt = (qs + 128) / 64;

    CP_WAIT0();
    __syncthreads();
    uint32_t qa_r[8][4], qla_r[8][4];
#pragma unroll
    for (int kf = 0; kf < 8; kf++) {
        ldsm4(qa_r[kf], q_addr + kf * 32);
        ldsm4(qla_r[kf], q_addr + FL_QLO + kf * 32);
    }

    for (int jt = 0; jt < nkt; jt++) {
        CP_WAIT0();
        __syncthreads();
        if (jt + 1 < nkt) { load_kv((jt + 1) & 1, (jt + 1) * 64); CP_COMMIT(); }

        const int ks = jt * 64;
        if (ks <= qs + w * 16 + 15) {
            const uint32_t kb = sb + FL_KV0 + (jt & 1) * FL_STG;

            float s[8][4];
#pragma unroll
            for (int i = 0; i < 8; i++)
#pragma unroll
                for (int j = 0; j < 4; j++) s[i][j] = 0.f;

#pragma unroll
            for (int kf = 0; kf < 8; kf++) {
#pragma unroll
                for (int nfp = 0; nfp < 4; nfp++) {
                    uint32_t kh4[4];
                    ldsm4(kh4, kb + (nfp * 16 + krow) * FL_ROWB + kcolb + kf * 32);
                    mma_f16(s[2 * nfp], qa_r[kf], kh4);
                    mma_f16(s[2 * nfp], qla_r[kf], kh4);
                    mma_f16(s[2 * nfp + 1], qa_r[kf], kh4 + 2);
                    mma_f16(s[2 * nfp + 1], qla_r[kf], kh4 + 2);
                }
            }

            if (ks + 63 > r0g) {
#pragma unroll
                for (int nf = 0; nf < 8; nf++) {
                    const int kc = ks + nf * 8 + (lane & 3) * 2;
                    if (kc > r0g)     s[nf][0] = -1e30f;
                    if (kc + 1 > r0g) s[nf][1] = -1e30f;
                    if (kc > r1g)     s[nf][2] = -1e30f;
                    if (kc + 1 > r1g) s[nf][3] = -1e30f;
                }
            }

            float m0l = -INFINITY, m1l = -INFINITY;
#pragma unroll
            for (int nf = 0; nf < 8; nf++) {
                m0l = fmaxf(m0l, fmaxf(s[nf][0], s[nf][1]));
                m1l = fmaxf(m1l, fmaxf(s[nf][2], s[nf][3]));
            }
            m0l = fmaxf(m0l, __shfl_xor_sync(0xffffffffu, m0l, 1));
            m0l = fmaxf(m0l, __shfl_xor_sync(0xffffffffu, m0l, 2));
            m1l = fmaxf(m1l, __shfl_xor_sync(0xffffffffu, m1l, 1));
            m1l = fmaxf(m1l, __shfl_xor_sync(0xffffffffu, m1l, 2));
            const float m0n = fmaxf(m0, m0l), m1n = fmaxf(m1, m1l);
            const float a0 = ex2((m0 - m0n) * SL2E);
            const float a1 = ex2((m1 - m1n) * SL2E);
            m0 = m0n; m1 = m1n;

            float sum0 = 0.f, sum1 = 0.f;
#pragma unroll
            for (int nf = 0; nf < 8; nf++) {
                s[nf][0] = ex2((s[nf][0] - m0n) * SL2E); sum0 += s[nf][0];
                s[nf][1] = ex2((s[nf][1] - m0n) * SL2E); sum0 += s[nf][1];
                s[nf][2] = ex2((s[nf][2] - m1n) * SL2E); sum1 += s[nf][2];
                s[nf][3] = ex2((s[nf][3] - m1n) * SL2E); sum1 += s[nf][3];
            }
            sum0 += __shfl_xor_sync(0xffffffffu, sum0, 1);
            sum0 += __shfl_xor_sync(0xffffffffu, sum0, 2);
            sum1 += __shfl_xor_sync(0xffffffffu, sum1, 1);
            sum1 += __shfl_xor_sync(0xffffffffu, sum1, 2);
            l0 = l0 * a0 + sum0;
            l1 = l1 * a1 + sum1;

#pragma unroll
            for (int nf = 0; nf < 16; nf++) {
                o[nf][0] *= a0; o[nf][1] *= a0;
                o[nf][2] *= a1; o[nf][3] *= a1;
            }

            const uint32_t vb = kb + FL_TILE;
#pragma unroll
            for (int kf2 = 0; kf2 < 4; kf2++) {
                uint32_t ah[4];
#pragma unroll
                for (int q2 = 0; q2 < 2; q2++) {
                    const float* sp = s[2 * kf2 + q2];
                    ah[q2 * 2 + 0] = pack_f16x2(sp[0], sp[1]);
                    ah[q2 * 2 + 1] = pack_f16x2(sp[2], sp[3]);
                }
#pragma unroll
                for (int nfp = 0; nfp < 8; nfp++) {
                    uint32_t vh4[4];
                    ldsm4t(vh4, vb + (kf2 * 16 + vrow) * FL_ROWB + vcolb + nfp * 32);
                    mma_f16(o[2 * nfp], ah, vh4);
                    mma_f16(o[2 * nfp + 1], ah, vh4 + 2);
                }
            }
        }
    }

    const float il0 = 1.f / l0, il1 = 1.f / l1;
    const size_t yb = hb + (size_t)r0g * EMB + (lane & 3) * 2;
#pragma unroll
    for (int nf = 0; nf < 16; nf++) {
        *(uint32_t*)(Y + yb + nf * 8) =
            pack_f16x2(o[nf][0] * il0, o[nf][1] * il0);
        *(uint32_t*)(Y + yb + (size_t)8 * EMB + nf * 8) =
            pack_f16x2(o[nf][2] * il1, o[nf][3] * il1);
    }
}

// =====================================================================
// launch
// =====================================================================
extern "C" void kernel_launch(void* const* d_in, const int* in_sizes, int n_in,
                              void* d_out, int out_size)
{
    const float* x  = (const float*)d_in[0];
    const float* wq = (const float*)d_in[1];
    const float* wk = (const float*)d_in[2];
    const float* wv = (const float*)d_in[3];
    const float* wo = (const float*)d_in[4];
    float* out = (float*)d_out;

    float *ct, *st;
    __half *ga, *wthi, *wtlo, *qh, *ql, *kh, *vh;
    cudaGetSymbolAddress((void**)&ct, g_cos);
    cudaGetSymbolAddress((void**)&st, g_sin);
    cudaGetSymbolAddress((void**)&ga, g_a);
    cudaGetSymbolAddress((void**)&wthi, g_wthi);
    cudaGetSymbolAddress((void**)&wtlo, g_wtlo);
    cudaGetSymbolAddress((void**)&qh, g_qh);
    cudaGetSymbolAddress((void**)&ql, g_ql);
    cudaGetSymbolAddress((void**)&kh, g_kh);
    cudaGetSymbolAddress((void**)&vh, g_vh);

    cudaFuncSetAttribute(mma_gemm_qkv_kernel,
                         cudaFuncAttributeMaxDynamicSharedMemorySize, GEMM_SMEM);
    cudaFuncSetAttribute(mma_gemm_out_kernel,
                         cudaFuncAttributeMaxDynamicSharedMemorySize, GEMM_SMEM);
    cudaFuncSetAttribute(flash_mma_kernel,
                         cudaFuncAttributeMaxDynamicSharedMemorySize, FL_SMEM);

    const int n4 = (int)(ELEMS / 4);
    const dim3 sgrid((n4 + 255) / 256);
    const size_t WSZ = (size_t)EMB * EMB;

    // prep: rope tables, x -> fp16, all 4 weights (x64, hi/lo) in one launch
    rope_table_kernel<<<(SEQ * 64 + 255) / 256, 256>>>(ct, st);
    conv16_kernel<<<sgrid, 256>>>(x, ga, n4);
    dim3 wgrid(EMB / 32, EMB / 32, 4);
    wsplit4_kernel<<<wgrid, 256>>>(wq, wk, wv, wo, wthi, wtlo);

    // fused QKV GEMM + rope/RMS epilogue (Q hi/lo, K single, V single)
    dim3 qkvgrid(3 * EMB / BN, MROWS / BM);   // (24, 64)
    mma_gemm_qkv_kernel<<<qkvgrid, 256, GEMM_SMEM>>>(
        ga, wthi, wtlo, qh, ql, kh, vh, ct, st);

    // flash attention -> writes ga (fp16 single) directly
    dim3 fgrid(SEQ / 128, NHEAD, BATCH);
    flash_mma_kernel<<<fgrid, 256, FL_SMEM>>>(qh, ql, kh, vh, ga);

    // out = y @ wo
    dim3 ogrid(EMB / BN, MROWS / BM);
    mma_gemm_out_kernel<<<ogrid, 256, GEMM_SMEM>>>(
        ga, wthi + 3 * WSZ, wtlo + 3 * WSZ, out);
}

// round 16
// speedup vs baseline: 1.6424x; 1.6424x over previous
#include <cuda_runtime.h>
#include <cuda_bf16.h>
#include <cuda_fp16.h>
#include <math.h>
#include <stdint.h>

// ---------------- constants ----------------
#define BATCH 4
#define SEQ   2048
#define EMB   2048
#define NHEAD 16
#define HDIM  128
#define MROWS (BATCH*SEQ)               // 8192
#define ELEMS ((size_t)BATCH*SEQ*EMB)   // 16777216
#define RMS_EPS 1.1920929e-07f
// softmax: exp(s*scale) = exp2(s * SL2E), SL2E = (1/sqrt(128))*log2(e)
#define SL2E 0.1275290959651556f
#define WSCALE 64.0f
#define WINV   0.015625f

// ---------------- scratch (device globals: allocation-free) ----------------
__device__ float g_q[ELEMS];
__device__ float g_k[ELEMS];
__device__ __half g_a[ELEMS];                      // fp16 A operand (x, then Y)
__device__ __half g_wthi[(size_t)4*EMB*EMB];       // transposed weights (x64), fp16
__device__ __half g_qh[ELEMS];
__device__ __half g_ql[ELEMS];
__device__ __half g_kh[ELEMS];                     // K single fp16
__device__ __half g_vh[ELEMS];                     // V single fp16
__device__ float g_cos[SEQ*64];
__device__ float g_sin[SEQ*64];

// =====================================================================
// PTX helpers (standard sm_80+ instructions; valid on plain sm_103)
// =====================================================================
__device__ __forceinline__ uint32_t smem_to_u32(const void* p) {
    uint32_t a;
    asm("{ .reg .u64 t; cvta.to.shared.u64 t, %1; cvt.u32.u64 %0, t; }"
        : "=r"(a) : "l"(p));
    return a;
}

__device__ __forceinline__ void ldsm4(uint32_t* r, uint32_t addr) {
    asm volatile("ldmatrix.sync.aligned.m8n8.x4.shared.b16 {%0,%1,%2,%3}, [%4];"
        : "=r"(r[0]), "=r"(r[1]), "=r"(r[2]), "=r"(r[3]) : "r"(addr));
}
__device__ __forceinline__ void ldsm4t(uint32_t* r, uint32_t addr) {
    asm volatile("ldmatrix.sync.aligned.m8n8.x4.trans.shared.b16 {%0,%1,%2,%3}, [%4];"
        : "=r"(r[0]), "=r"(r[1]), "=r"(r[2]), "=r"(r[3]) : "r"(addr));
}

__device__ __forceinline__ void mma_f16(float* c, const uint32_t* a, const uint32_t* b) {
    asm volatile(
        "mma.sync.aligned.m16n8k16.row.col.f32.f16.f16.f32 "
        "{%0,%1,%2,%3}, {%4,%5,%6,%7}, {%8,%9}, {%0,%1,%2,%3};"
        : "+f"(c[0]), "+f"(c[1]), "+f"(c[2]), "+f"(c[3])
        : "r"(a[0]), "r"(a[1]), "r"(a[2]), "r"(a[3]), "r"(b[0]), "r"(b[1]));
}

__device__ __forceinline__ uint32_t pack_f16x2(float lo, float hi) {
    __half2 h = __floats2half2_rn(lo, hi);
    return *(uint32_t*)&h;
}

// fast exp2 (single SASS MUFU.EX2)
__device__ __forceinline__ float ex2(float x) {
    float y;
    asm("ex2.approx.f32 %0, %1;" : "=f"(y) : "f"(x));
    return y;
}

#define CP_ASYNC16(dst, src) \
    asm volatile("cp.async.cg.shared.global [%0], [%1], 16;" :: "r"(dst), "l"(src) : "memory")
#define CP_COMMIT() asm volatile("cp.async.commit_group;" ::: "memory")
#define CP_WAIT0()  asm volatile("cp.async.wait_group 0;" ::: "memory")

// =====================================================================
// conv16: fp32 -> fp16 (single)
// =====================================================================
__global__ __launch_bounds__(256) void conv16_kernel(
    const float* __restrict__ in, __half* __restrict__ out, int n4)
{
    int i = blockIdx.x * 256 + threadIdx.x;
    if (i >= n4) return;
    float4 v = ((const float4*)in)[i];
    uint2 o;
    o.x = pack_f16x2(v.x, v.y);
    o.y = pack_f16x2(v.z, v.w);
    ((uint2*)out)[i] = o;
}

// =====================================================================
// 4 weights: transpose + x64 scale -> fp16 single
// =====================================================================
__global__ __launch_bounds__(256) void wsplit4_kernel(
    const float* __restrict__ w0, const float* __restrict__ w1,
    const float* __restrict__ w2, const float* __restrict__ w3,
    __half* __restrict__ hi_base)
{
    __shared__ float tile[32][33];
    const int z = blockIdx.z;
    const float* w = (z == 0) ? w0 : (z == 1) ? w1 : (z == 2) ? w2 : w3;
    __half* hi = hi_base + (size_t)z * EMB * EMB;

    int n0 = blockIdx.x * 32, k0 = blockIdx.y * 32;
    int tx = threadIdx.x & 31, ty = threadIdx.x >> 5;
#pragma unroll
    for (int i = 0; i < 32; i += 8)
        tile[ty + i][tx] = w[(size_t)(k0 + ty + i) * EMB + n0 + tx];
    __syncthreads();
#pragma unroll
    for (int i = 0; i < 32; i += 8) {
        float v = tile[tx][ty + i] * WSCALE;
        size_t o = (size_t)(n0 + ty + i) * EMB + k0 + tx;
        hi[o] = __float2half_rn(v);
    }
}

// =====================================================================
// RoPE table precompute (double precision, once)
// =====================================================================
__global__ __launch_bounds__(256) void rope_table_kernel(
    float* __restrict__ ct, float* __restrict__ st)
{
    const int idx = blockIdx.x * 256 + threadIdx.x;
    if (idx >= SEQ * 64) return;
    const int tp = idx >> 6, i = idx & 63;
    double inv = exp(-((double)i / 64.0) * log(10000.0));
    double ang = (double)tp * inv;
    double sd, cd;
    sincos(ang, &sd, &cd);
    ct[idx] = (float)cd;
    st[idx] = (float)sd;
}

// =====================================================================
// mma.sync GEMM: C = (A * B^T)/64.  A, B single fp16 (1 chain).
// 2-stage cp.async, ONE sync per k-iter.
// Block tile 128x256x64, 8 warps (2 x 4), warp tile 64x64.
// mode 0: fp32 -> c0.  mode 1 (QKV fused, N=6144): q,k fp32; V fp16 single.
// =====================================================================
#define BM 128
#define BN 256
#define BK 64
#define RSTRB 144
#define TA (128 * RSTRB)          // 18432 (A tile)
#define TB (256 * RSTRB)          // 36864 (B tile)
#define STG_B (TA + TB)           // 55296
#define GEMM_SMEM (2 * STG_B)     // 110592

__global__ __launch_bounds__(256) void mma_gemm_kernel(
    const __half* __restrict__ A, const __half* __restrict__ B,
    int K, int mode,
    float* __restrict__ c0, float* __restrict__ c1,
    __half* __restrict__ c2)
{
    extern __shared__ char smc[];
    const uint32_t sb = smem_to_u32(smc);
    const int t = threadIdx.x;
    const int lane = t & 31;
    const int wid = t >> 5;
    const int warp_m = wid & 1;
    const int warp_n = wid >> 1;
    const int row0 = blockIdx.y * BM;
    const int col0 = blockIdx.x * BN;

    float acc[4][8][4];
#pragma unroll
    for (int i = 0; i < 4; i++)
#pragma unroll
        for (int j = 0; j < 8; j++)
#pragma unroll
            for (int r = 0; r < 4; r++) acc[i][j][r] = 0.f;

    auto load_stage = [&](int s, int k0) {
        const uint32_t base = sb + s * STG_B;
#pragma unroll
        for (int i = 0; i < 4; i++) {
            const int idx = t + i * 256;
            const int r = idx >> 3, c = idx & 7;
            CP_ASYNC16(base + r * RSTRB + c * 16,
                       A + (size_t)(row0 + r) * K + k0 + c * 8);
        }
#pragma unroll
        for (int i = 0; i < 8; i++) {
            const int idx = t + i * 256;
            const int r = idx >> 3, c = idx & 7;
            CP_ASYNC16(base + TA + r * RSTRB + c * 16,
                       B + (size_t)(col0 + r) * K + k0 + c * 8);
        }
    };

    const int nIter = K / BK;
    load_stage(0, 0);
    CP_COMMIT();

    for (int it = 0; it < nIter; it++) {
        CP_WAIT0();
        __syncthreads();
        if (it + 1 < nIter) {
            load_stage((it + 1) & 1, (it + 1) * BK);
            CP_COMMIT();
        }

        const uint32_t abase = sb + (it & 1) * STG_B;
        const uint32_t bbase = abase + TA;
        const int arow = warp_m * 64 + (lane & 15);
        const int brow = warp_n * 64 + ((lane >> 4) << 3) + (lane & 7);

#pragma unroll
        for (int ks = 0; ks < 4; ks++) {
            uint32_t ah[4][4], bh[4][4];
            const uint32_t acol = ks * 32 + ((lane >> 4) << 4);
            const uint32_t bcol = ks * 32 + (((lane >> 3) & 1) << 4);
#pragma unroll
            for (int mf = 0; mf < 4; mf++)
                ldsm4(ah[mf], abase + (arow + mf * 16) * RSTRB + acol);
#pragma unroll
            for (int bf = 0; bf < 4; bf++)
                ldsm4(bh[bf], bbase + (brow + bf * 16) * RSTRB + bcol);
#pragma unroll
            for (int mf = 0; mf < 4; mf++) {
#pragma unroll
                for (int nf = 0; nf < 8; nf++) {
                    mma_f16(acc[mf][nf], ah[mf], &bh[nf >> 1][(nf & 1) * 2]);
                }
            }
        }
    }

    // ---- epilogue (unscale by 1/64) ----
    const int mbase = row0 + warp_m * 64 + (lane >> 2);
    const int nb = col0 + warp_n * 64 + (lane & 3) * 2;
#pragma unroll
    for (int mf = 0; mf < 4; mf++) {
#pragma unroll
        for (int nf = 0; nf < 8; nf++) {
            const int n = nb + nf * 8;
            const int m0 = mbase + mf * 16;
            float a0 = acc[mf][nf][0] * WINV, a1 = acc[mf][nf][1] * WINV;
            float a2 = acc[mf][nf][2] * WINV, a3 = acc[mf][nf][3] * WINV;
            if (mode == 0) {
                const size_t o0 = (size_t)m0 * EMB + n;
                *(float2*)(c0 + o0) = make_float2(a0, a1);
                *(float2*)(c0 + o0 + 8 * EMB) = make_float2(a2, a3);
            } else {
                const int which = n >> 11;
                const int nloc = n & 2047;
                const size_t o0 = (size_t)m0 * EMB + nloc;
                if (which == 0) {
                    *(float2*)(c0 + o0) = make_float2(a0, a1);
                    *(float2*)(c0 + o0 + 8 * EMB) = make_float2(a2, a3);
                } else if (which == 1) {
                    *(float2*)(c1 + o0) = make_float2(a0, a1);
                    *(float2*)(c1 + o0 + 8 * EMB) = make_float2(a2, a3);
                } else {
                    *(uint32_t*)(c2 + o0) = pack_f16x2(a0, a1);
                    *(uint32_t*)(c2 + o0 + 8 * EMB) = pack_f16x2(a2, a3);
                }
            }
        }
    }
}

// =====================================================================
// RoPE + RMSNorm: Q -> fp16 hi/lo, K -> fp16 single.
// One WARP per (buffer, b, t, h) head-row; Q and K in one launch.
// =====================================================================
__global__ __launch_bounds__(256) void ropeprep2_kernel(
    const float* __restrict__ q, const float* __restrict__ k,
    const float* __restrict__ ct, const float* __restrict__ st,
    __half* __restrict__ qh, __half* __restrict__ ql,
    __half* __restrict__ kh)
{
    const int w = blockIdx.x * 8 + (threadIdx.x >> 5);
    const int lane = threadIdx.x & 31;
    const int sel = w >> 17;            // 0=Q, 1=K
    const int w2 = w & 131071;
    const int b = w2 >> 15;
    const int r = w2 & 32767;
    const int tp = r >> 4;
    const int h = r & 15;

    const float* buf = sel ? k : q;
    const size_t base = ((size_t)b * SEQ + tp) * EMB + (size_t)h * HDIM;

    const float x1a = buf[base + lane];
    const float x1b = buf[base + 32 + lane];
    const float x2a = buf[base + 64 + lane];
    const float x2b = buf[base + 96 + lane];
    const float ca = ct[tp * 64 + lane],      sa  = st[tp * 64 + lane];
    const float cb = ct[tp * 64 + 32 + lane], sb2 = st[tp * 64 + 32 + lane];

    const float n1a = x1a * ca - x2a * sa;
    const float n2a = x1a * sa + x2a * ca;
    const float n1b = x1b * cb - x2b * sb2;
    const float n2b = x1b * sb2 + x2b * cb;

    float sq = n1a * n1a + n2a * n2a + n1b * n1b + n2b * n2b;
#pragma unroll
    for (int o = 16; o > 0; o >>= 1)
        sq += __shfl_xor_sync(0xffffffffu, sq, o);

    const float rs = rsqrtf(sq * (1.0f / 128.0f) + RMS_EPS);

    const float y0 = n1a * rs, y1 = n1b * rs, y2 = n2a * rs, y3 = n2b * rs;
    if (sel) {
        kh[base + lane]      = __float2half_rn(y0);
        kh[base + 32 + lane] = __float2half_rn(y1);
        kh[base + 64 + lane] = __float2half_rn(y2);
        kh[base + 96 + lane] = __float2half_rn(y3);
    } else {
        __half h0 = __float2half_rn(y0);
        __half h1 = __float2half_rn(y1);
        __half h2 = __float2half_rn(y2);
        __half h3 = __float2half_rn(y3);
        qh[base + lane]      = h0;
        qh[base + 32 + lane] = h1;
        qh[base + 64 + lane] = h2;
        qh[base + 96 + lane] = h3;
        ql[base + lane]      = __float2half_rn(y0 - __half2float(h0));
        ql[base + 32 + lane] = __float2half_rn(y1 - __half2float(h1));
        ql[base + 64 + lane] = __float2half_rn(y2 - __half2float(h2));
        ql[base + 96 + lane] = __float2half_rn(y3 - __half2float(h3));
    }
}

// =====================================================================
// Flash attention (unchanged from R14): S = 2 chains (Qh,Ql x K single),
// P·V = 1 chain. Q fragments in registers. Output fp16 single.
// =====================================================================
#define FL_STR  136
#define FL_ROWB (FL_STR*2)
#define FL_TILE (64*FL_ROWB)            // 17408
#define FL_STG  (2*FL_TILE)             // 34816
#define FL_QLO  (128*FL_ROWB)           // 34816
#define FL_KV0  (4*FL_TILE)             // 69632 (after Q hi+lo)
#define FL_SMEM (4*FL_TILE + 2*FL_STG)  // 139264

__global__ __launch_bounds__(256, 1) void flash_mma_kernel(
    const __half* __restrict__ Qh, const __half* __restrict__ Ql,
    const __half* __restrict__ Kh, const __half* __restrict__ Vh,
    __half* __restrict__ Y)
{
    extern __shared__ char smc[];
    const uint32_t sb = smem_to_u32(smc);
    const int t = threadIdx.x;
    const int lane = t & 31;
    const int w = t >> 5;
    const int qi = gridDim.x - 1 - blockIdx.x;
    const int h = blockIdx.y, b = blockIdx.z;
    const int qs = qi * 128;
    const size_t hb = ((size_t)b * SEQ) * EMB + (size_t)h * HDIM;

#pragma unroll
    for (int i = 0; i < 8; i++) {
        const int idx = t + i * 256;
        const int r = idx >> 4, c = idx & 15;
        const size_t g = hb + (size_t)(qs + r) * EMB + c * 8;
        CP_ASYNC16(sb + r * FL_ROWB + c * 16, Qh + g);
        CP_ASYNC16(sb + FL_QLO + r * FL_ROWB + c * 16, Ql + g);
    }
    CP_COMMIT();

    auto load_kv = [&](int s, int ks) {
        const uint32_t base = sb + FL_KV0 + s * FL_STG;
#pragma unroll
        for (int i = 0; i < 4; i++) {
            const int idx = t + i * 256;
            const int r = idx >> 4, c = idx & 15;
            const size_t g = hb + (size_t)(ks + r) * EMB + c * 8;
            CP_ASYNC16(base + r * FL_ROWB + c * 16, Kh + g);
            CP_ASYNC16(base + FL_TILE + r * FL_ROWB + c * 16, Vh + g);
        }
    };

    load_kv(0, 0);
    CP_COMMIT();

    float m0 = -INFINITY, m1 = -INFINITY, l0 = 0.f, l1 = 0.f;
    float o[16][4];
#pragma unroll
    for (int i = 0; i < 16; i++)
#pragma unroll
        for (int j = 0; j < 4; j++) o[i][j] = 0.f;

    const uint32_t q_addr = sb + (w * 16 + (lane & 15)) * FL_ROWB + (lane >> 4) * 16;
    const int krow = (lane & 7) + ((lane >> 4) << 3);
    const uint32_t kcolb = ((lane >> 3) & 1) * 16;
    const int vrow = (lane & 7) + (((lane >> 3) & 1) << 3);
    const uint32_t vcolb = (lane >> 4) * 16;

    const int r0g = qs + w * 16 + (lane >> 2);
    const int r1g = r0g + 8;
    const int nkt = (qs + 128) / 64;

    CP_WAIT0();
    __syncthreads();
    uint32_t qa_r[8][4], qla_r[8][4];
#pragma unroll
    for (int kf = 0; kf < 8; kf++) {
        ldsm4(qa_r[kf], q_addr + kf * 32);
        ldsm4(qla_r[kf], q_addr + FL_QLO + kf * 32);
    }

    for (int jt = 0; jt < nkt; jt++) {
        CP_WAIT0();
        __syncthreads();
        if (jt + 1 < nkt) { load_kv((jt + 1) & 1, (jt + 1) * 64); CP_COMMIT(); }

        const int ks = jt * 64;
        if (ks <= qs + w * 16 + 15) {
            const uint32_t kb = sb + FL_KV0 + (jt & 1) * FL_STG;

            float s[8][4];
#pragma unroll
            for (int i = 0; i < 8; i++)
#pragma unroll
                for (int j = 0; j < 4; j++) s[i][j] = 0.f;

#pragma unroll
            for (int kf = 0; kf < 8; kf++) {
#pragma unroll
                for (int nfp = 0; nfp < 4; nfp++) {
                    uint32_t kh4[4];
                    ldsm4(kh4, kb + (nfp * 16 + krow) * FL_ROWB + kcolb + kf * 32);
                    mma_f16(s[2 * nfp], qa_r[kf], kh4);
                    mma_f16(s[2 * nfp], qla_r[kf], kh4);
                    mma_f16(s[2 * nfp + 1], qa_r[kf], kh4 + 2);
                    mma_f16(s[2 * nfp + 1], qla_r[kf], kh4 + 2);
                }
            }

            if (ks + 63 > r0g) {
#pragma unroll
                for (int nf = 0; nf < 8; nf++) {
                    const int kc = ks + nf * 8 + (lane & 3) * 2;
                    if (kc > r0g)     s[nf][0] = -1e30f;
                    if (kc + 1 > r0g) s[nf][1] = -1e30f;
                    if (kc > r1g)     s[nf][2] = -1e30f;
                    if (kc + 1 > r1g) s[nf][3] = -1e30f;
                }
            }

            float m0l = -INFINITY, m1l = -INFINITY;
#pragma unroll
            for (int nf = 0; nf < 8; nf++) {
                m0l = fmaxf(m0l, fmaxf(s[nf][0], s[nf][1]));
                m1l = fmaxf(m1l, fmaxf(s[nf][2], s[nf][3]));
            }
            m0l = fmaxf(m0l, __shfl_xor_sync(0xffffffffu, m0l, 1));
            m0l = fmaxf(m0l, __shfl_xor_sync(0xffffffffu, m0l, 2));
            m1l = fmaxf(m1l, __shfl_xor_sync(0xffffffffu, m1l, 1));
            m1l = fmaxf(m1l, __shfl_xor_sync(0xffffffffu, m1l, 2));
            const float m0n = fmaxf(m0, m0l), m1n = fmaxf(m1, m1l);
            const float a0 = ex2((m0 - m0n) * SL2E);
            const float a1 = ex2((m1 - m1n) * SL2E);
            m0 = m0n; m1 = m1n;

            float sum0 = 0.f, sum1 = 0.f;
#pragma unroll
            for (int nf = 0; nf < 8; nf++) {
                s[nf][0] = ex2((s[nf][0] - m0n) * SL2E); sum0 += s[nf][0];
                s[nf][1] = ex2((s[nf][1] - m0n) * SL2E); sum0 += s[nf][1];
                s[nf][2] = ex2((s[nf][2] - m1n) * SL2E); sum1 += s[nf][2];
                s[nf][3] = ex2((s[nf][3] - m1n) * SL2E); sum1 += s[nf][3];
            }
            sum0 += __shfl_xor_sync(0xffffffffu, sum0, 1);
            sum0 += __shfl_xor_sync(0xffffffffu, sum0, 2);
            sum1 += __shfl_xor_sync(0xffffffffu, sum1, 1);
            sum1 += __shfl_xor_sync(0xffffffffu, sum1, 2);
            l0 = l0 * a0 + sum0;
            l1 = l1 * a1 + sum1;

#pragma unroll
            for (int nf = 0; nf < 16; nf++) {
                o[nf][0] *= a0; o[nf][1] *= a0;
                o[nf][2] *= a1; o[nf][3] *= a1;
            }

            const uint32_t vb = kb + FL_TILE;
#pragma unroll
            for (int kf2 = 0; kf2 < 4; kf2++) {
                uint32_t ah[4];
#pragma unroll
                for (int q2 = 0; q2 < 2; q2++) {
                    const float* sp = s[2 * kf2 + q2];
                    ah[q2 * 2 + 0] = pack_f16x2(sp[0], sp[1]);
                    ah[q2 * 2 + 1] = pack_f16x2(sp[2], sp[3]);
                }
#pragma unroll
                for (int nfp = 0; nfp < 8; nfp++) {
                    uint32_t vh4[4];
                    ldsm4t(vh4, vb + (kf2 * 16 + vrow) * FL_ROWB + vcolb + nfp * 32);
                    mma_f16(o[2 * nfp], ah, vh4);
                    mma_f16(o[2 * nfp + 1], ah, vh4 + 2);
                }
            }
        }
    }

    const float il0 = 1.f / l0, il1 = 1.f / l1;
    const size_t yb = hb + (size_t)r0g * EMB + (lane & 3) * 2;
#pragma unroll
    for (int nf = 0; nf < 16; nf++) {
        *(uint32_t*)(Y + yb + nf * 8) =
            pack_f16x2(o[nf][0] * il0, o[nf][1] * il0);
        *(uint32_t*)(Y + yb + (size_t)8 * EMB + nf * 8) =
            pack_f16x2(o[nf][2] * il1, o[nf][3] * il1);
    }
}

// =====================================================================
// launch
// =====================================================================
extern "C" void kernel_launch(void* const* d_in, const int* in_sizes, int n_in,
                              void* d_out, int out_size)
{
    const float* x  = (const float*)d_in[0];
    const float* wq = (const float*)d_in[1];
    const float* wk = (const float*)d_in[2];
    const float* wv = (const float*)d_in[3];
    const float* wo = (const float*)d_in[4];
    float* out = (float*)d_out;

    float *gq, *gk, *ct, *st;
    __half *ga, *wthi, *qh, *ql, *kh, *vh;
    cudaGetSymbolAddress((void**)&gq, g_q);
    cudaGetSymbolAddress((void**)&gk, g_k);
    cudaGetSymbolAddress((void**)&ct, g_cos);
    cudaGetSymbolAddress((void**)&st, g_sin);
    cudaGetSymbolAddress((void**)&ga, g_a);
    cudaGetSymbolAddress((void**)&wthi, g_wthi);
    cudaGetSymbolAddress((void**)&qh, g_qh);
    cudaGetSymbolAddress((void**)&ql, g_ql);
    cudaGetSymbolAddress((void**)&kh, g_kh);
    cudaGetSymbolAddress((void**)&vh, g_vh);

    cudaFuncSetAttribute(mma_gemm_kernel,
                         cudaFuncAttributeMaxDynamicSharedMemorySize, GEMM_SMEM);
    cudaFuncSetAttribute(flash_mma_kernel,
                         cudaFuncAttributeMaxDynamicSharedMemorySize, FL_SMEM);

    const int n4 = (int)(ELEMS / 4);
    const dim3 sgrid((n4 + 255) / 256);
    const size_t WSZ = (size_t)EMB * EMB;

    // prep: rope tables, x -> fp16, all 4 weights (x64, fp16) in one launch
    rope_table_kernel<<<(SEQ * 64 + 255) / 256, 256>>>(ct, st);
    conv16_kernel<<<sgrid, 256>>>(x, ga, n4);
    dim3 wgrid(EMB / 32, EMB / 32, 4);
    wsplit4_kernel<<<wgrid, 256>>>(wq, wk, wv, wo, wthi);

    // fused QKV GEMM: q,k fp32; v directly fp16 single
    dim3 qkvgrid(3 * EMB / BN, MROWS / BM);   // (24, 64)
    mma_gemm_kernel<<<qkvgrid, 256, GEMM_SMEM>>>(
        ga, wthi, EMB, 1, gq, gk, vh);

    // RoPE + RMSNorm: Q -> hi/lo, K -> single
    ropeprep2_kernel<<<2 * BATCH * SEQ * NHEAD / 8, 256>>>(
        gq, gk, ct, st, qh, ql, kh);

    // flash attention -> writes ga (fp16 single) directly
    dim3 fgrid(SEQ / 128, NHEAD, BATCH);
    flash_mma_kernel<<<fgrid, 256, FL_SMEM>>>(qh, ql, kh, vh, ga);

    // out = y @ wo
    dim3 ogrid(EMB / BN, MROWS / BM);
    mma_gemm_kernel<<<ogrid, 256, GEMM_SMEM>>>(
        ga, wthi + 3 * WSZ, EMB, 0, out, nullptr, nullptr);
}

// round 17
// speedup vs baseline: 1.7528x; 1.0672x over previous
#include <cuda_runtime.h>
#include <cuda_bf16.h>
#include <cuda_fp16.h>
#include <math.h>
#include <stdint.h>

// ---------------- constants ----------------
#define BATCH 4
#define SEQ   2048
#define EMB   2048
#define NHEAD 16
#define HDIM  128
#define MROWS (BATCH*SEQ)               // 8192
#define ELEMS ((size_t)BATCH*SEQ*EMB)   // 16777216
#define RMS_EPS 1.1920929e-07f
#define SL2E 0.1275290959651556f
#define WSCALE 64.0f
#define WINV   0.015625f

// ---------------- scratch (device globals: allocation-free) ----------------
__device__ float g_q[ELEMS];
__device__ float g_k[ELEMS];
__device__ __half g_a[ELEMS];                      // fp16 A operand (x, then Y)
__device__ __half g_wthi[(size_t)4*EMB*EMB];       // transposed weights (x64), fp16
__device__ __half g_qh[ELEMS];                     // Q single fp16
__device__ __half g_kh[ELEMS];                     // K single fp16
__device__ __half g_vh[ELEMS];                     // V single fp16
__device__ float g_cos[SEQ*64];
__device__ float g_sin[SEQ*64];

// =====================================================================
// PTX helpers (standard sm_80+ instructions; valid on plain sm_103)
// =====================================================================
__device__ __forceinline__ uint32_t smem_to_u32(const void* p) {
    uint32_t a;
    asm("{ .reg .u64 t; cvta.to.shared.u64 t, %1; cvt.u32.u64 %0, t; }"
        : "=r"(a) : "l"(p));
    return a;
}

__device__ __forceinline__ void ldsm4(uint32_t* r, uint32_t addr) {
    asm volatile("ldmatrix.sync.aligned.m8n8.x4.shared.b16 {%0,%1,%2,%3}, [%4];"
        : "=r"(r[0]), "=r"(r[1]), "=r"(r[2]), "=r"(r[3]) : "r"(addr));
}
__device__ __forceinline__ void ldsm4t(uint32_t* r, uint32_t addr) {
    asm volatile("ldmatrix.sync.aligned.m8n8.x4.trans.shared.b16 {%0,%1,%2,%3}, [%4];"
        : "=r"(r[0]), "=r"(r[1]), "=r"(r[2]), "=r"(r[3]) : "r"(addr));
}

__device__ __forceinline__ void mma_f16(float* c, const uint32_t* a, const uint32_t* b) {
    asm volatile(
        "mma.sync.aligned.m16n8k16.row.col.f32.f16.f16.f32 "
        "{%0,%1,%2,%3}, {%4,%5,%6,%7}, {%8,%9}, {%0,%1,%2,%3};"
        : "+f"(c[0]), "+f"(c[1]), "+f"(c[2]), "+f"(c[3])
        : "r"(a[0]), "r"(a[1]), "r"(a[2]), "r"(a[3]), "r"(b[0]), "r"(b[1]));
}

__device__ __forceinline__ uint32_t pack_f16x2(float lo, float hi) {
    __half2 h = __floats2half2_rn(lo, hi);
    return *(uint32_t*)&h;
}

__device__ __forceinline__ float ex2(float x) {
    float y;
    asm("ex2.approx.f32 %0, %1;" : "=f"(y) : "f"(x));
    return y;
}

#define CP_ASYNC16(dst, src) \
    asm volatile("cp.async.cg.shared.global [%0], [%1], 16;" :: "r"(dst), "l"(src) : "memory")
#define CP_COMMIT() asm volatile("cp.async.commit_group;" ::: "memory")
#define CP_WAIT0()  asm volatile("cp.async.wait_group 0;" ::: "memory")

// =====================================================================
// conv16: fp32 -> fp16 (single)
// =====================================================================
__global__ __launch_bounds__(256) void conv16_kernel(
    const float* __restrict__ in, __half* __restrict__ out, int n4)
{
    int i = blockIdx.x * 256 + threadIdx.x;
    if (i >= n4) return;
    float4 v = ((const float4*)in)[i];
    uint2 o;
    o.x = pack_f16x2(v.x, v.y);
    o.y = pack_f16x2(v.z, v.w);
    ((uint2*)out)[i] = o;
}

// =====================================================================
// 4 weights: transpose + x64 scale -> fp16 single
// =====================================================================
__global__ __launch_bounds__(256) void wsplit4_kernel(
    const float* __restrict__ w0, const float* __restrict__ w1,
    const float* __restrict__ w2, const float* __restrict__ w3,
    __half* __restrict__ hi_base)
{
    __shared__ float tile[32][33];
    const int z = blockIdx.z;
    const float* w = (z == 0) ? w0 : (z == 1) ? w1 : (z == 2) ? w2 : w3;
    __half* hi = hi_base + (size_t)z * EMB * EMB;

    int n0 = blockIdx.x * 32, k0 = blockIdx.y * 32;
    int tx = threadIdx.x & 31, ty = threadIdx.x >> 5;
#pragma unroll
    for (int i = 0; i < 32; i += 8)
        tile[ty + i][tx] = w[(size_t)(k0 + ty + i) * EMB + n0 + tx];
    __syncthreads();
#pragma unroll
    for (int i = 0; i < 32; i += 8) {
        float v = tile[tx][ty + i] * WSCALE;
        size_t o = (size_t)(n0 + ty + i) * EMB + k0 + tx;
        hi[o] = __float2half_rn(v);
    }
}

// =====================================================================
// RoPE table precompute (double precision, once)
// =====================================================================
__global__ __launch_bounds__(256) void rope_table_kernel(
    float* __restrict__ ct, float* __restrict__ st)
{
    const int idx = blockIdx.x * 256 + threadIdx.x;
    if (idx >= SEQ * 64) return;
    const int tp = idx >> 6, i = idx & 63;
    double inv = exp(-((double)i / 64.0) * log(10000.0));
    double ang = (double)tp * inv;
    double sd, cd;
    sincos(ang, &sd, &cd);
    ct[idx] = (float)cd;
    st[idx] = (float)sd;
}

// =====================================================================
// mma.sync GEMM: C = (A * B^T)/64.  A, B single fp16 (1 chain).
// BK=128, 2-stage cp.async, ONE sync per k-iter (16 iters).
// Block tile 128x256x128, 8 warps (2 x 4), warp tile 64x64.
// mode 0: fp32 -> c0.  mode 1 (QKV fused, N=6144): q,k fp32; V fp16 single.
// =====================================================================
#define BM 128
#define BN 256
#define BK 128
#define RSTRB 272                 // 128 fp16 = 256 B + 16 pad
#define TA (128 * RSTRB)          // 34816
#define TB (256 * RSTRB)          // 69632
#define STG_B (TA + TB)           // 104448
#define GEMM_SMEM (2 * STG_B)     // 208896

__global__ __launch_bounds__(256) void mma_gemm_kernel(
    const __half* __restrict__ A, const __half* __restrict__ B,
    int K, int mode,
    float* __restrict__ c0, float* __restrict__ c1,
    __half* __restrict__ c2)
{
    extern __shared__ char smc[];
    const uint32_t sb = smem_to_u32(smc);
    const int t = threadIdx.x;
    const int lane = t & 31;
    const int wid = t >> 5;
    const int warp_m = wid & 1;
    const int warp_n = wid >> 1;
    const int row0 = blockIdx.y * BM;
    const int col0 = blockIdx.x * BN;

    float acc[4][8][4];
#pragma unroll
    for (int i = 0; i < 4; i++)
#pragma unroll
        for (int j = 0; j < 8; j++)
#pragma unroll
            for (int r = 0; r < 4; r++) acc[i][j][r] = 0.f;

    auto load_stage = [&](int s, int k0) {
        const uint32_t base = sb + s * STG_B;
        // A: 128 rows x 16 chunks = 2048 copies -> 8/thread
#pragma unroll
        for (int i = 0; i < 8; i++) {
            const int idx = t + i * 256;
            const int r = idx >> 4, c = idx & 15;
            CP_ASYNC16(base + r * RSTRB + c * 16,
                       A + (size_t)(row0 + r) * K + k0 + c * 8);
        }
        // B: 256 rows x 16 chunks = 4096 copies -> 16/thread
#pragma unroll
        for (int i = 0; i < 16; i++) {
            const int idx = t + i * 256;
            const int r = idx >> 4, c = idx & 15;
            CP_ASYNC16(base + TA + r * RSTRB + c * 16,
                       B + (size_t)(col0 + r) * K + k0 + c * 8);
        }
    };

    const int nIter = K / BK;     // 16
    load_stage(0, 0);
    CP_COMMIT();

    for (int it = 0; it < nIter; it++) {
        CP_WAIT0();
        __syncthreads();
        if (it + 1 < nIter) {
            load_stage((it + 1) & 1, (it + 1) * BK);
            CP_COMMIT();
        }

        const uint32_t abase = sb + (it & 1) * STG_B;
        const uint32_t bbase = abase + TA;
        const int arow = warp_m * 64 + (lane & 15);
        const int brow = warp_n * 64 + ((lane >> 4) << 3) + (lane & 7);

#pragma unroll
        for (int ks = 0; ks < 8; ks++) {
            uint32_t ah[4][4], bh[4][4];
            const uint32_t acol = ks * 32 + ((lane >> 4) << 4);
            const uint32_t bcol = ks * 32 + (((lane >> 3) & 1) << 4);
#pragma unroll
            for (int mf = 0; mf < 4; mf++)
                ldsm4(ah[mf], abase + (arow + mf * 16) * RSTRB + acol);
#pragma unroll
            for (int bf = 0; bf < 4; bf++)
                ldsm4(bh[bf], bbase + (brow + bf * 16) * RSTRB + bcol);
#pragma unroll
            for (int mf = 0; mf < 4; mf++) {
#pragma unroll
                for (int nf = 0; nf < 8; nf++) {
                    mma_f16(acc[mf][nf], ah[mf], &bh[nf >> 1][(nf & 1) * 2]);
                }
            }
        }
    }

    // ---- epilogue (unscale by 1/64) ----
    const int mbase = row0 + warp_m * 64 + (lane >> 2);
    const int nb = col0 + warp_n * 64 + (lane & 3) * 2;
#pragma unroll
    for (int mf = 0; mf < 4; mf++) {
#pragma unroll
        for (int nf = 0; nf < 8; nf++) {
            const int n = nb + nf * 8;
            const int m0 = mbase + mf * 16;
            float a0 = acc[mf][nf][0] * WINV, a1 = acc[mf][nf][1] * WINV;
            float a2 = acc[mf][nf][2] * WINV, a3 = acc[mf][nf][3] * WINV;
            if (mode == 0) {
                const size_t o0 = (size_t)m0 * EMB + n;
                *(float2*)(c0 + o0) = make_float2(a0, a1);
                *(float2*)(c0 + o0 + 8 * EMB) = make_float2(a2, a3);
            } else {
                const int which = n >> 11;
                const int nloc = n & 2047;
                const size_t o0 = (size_t)m0 * EMB + nloc;
                if (which == 0) {
                    *(float2*)(c0 + o0) = make_float2(a0, a1);
                    *(float2*)(c0 + o0 + 8 * EMB) = make_float2(a2, a3);
                } else if (which == 1) {
                    *(float2*)(c1 + o0) = make_float2(a0, a1);
                    *(float2*)(c1 + o0 + 8 * EMB) = make_float2(a2, a3);
                } else {
                    *(uint32_t*)(c2 + o0) = pack_f16x2(a0, a1);
                    *(uint32_t*)(c2 + o0 + 8 * EMB) = pack_f16x2(a2, a3);
                }
            }
        }
    }
}

// =====================================================================
// RoPE + RMSNorm: Q and K both -> fp16 single.
// One WARP per (buffer, b, t, h) head-row; Q and K in one launch.
// =====================================================================
__global__ __launch_bounds__(256) void ropeprep2_kernel(
    const float* __restrict__ q, const float* __restrict__ k,
    const float* __restrict__ ct, const float* __restrict__ st,
    __half* __restrict__ qh, __half* __restrict__ kh)
{
    const int w = blockIdx.x * 8 + (threadIdx.x >> 5);
    const int lane = threadIdx.x & 31;
    const int sel = w >> 17;            // 0=Q, 1=K
    const int w2 = w & 131071;
    const int b = w2 >> 15;
    const int r = w2 & 32767;
    const int tp = r >> 4;
    const int h = r & 15;

    const float* buf = sel ? k : q;
    const size_t base = ((size_t)b * SEQ + tp) * EMB + (size_t)h * HDIM;

    const float x1a = buf[base + lane];
    const float x1b = buf[base + 32 + lane];
    const float x2a = buf[base + 64 + lane];
    const float x2b = buf[base + 96 + lane];
    const float ca = ct[tp * 64 + lane],      sa  = st[tp * 64 + lane];
    const float cb = ct[tp * 64 + 32 + lane], sb2 = st[tp * 64 + 32 + lane];

    const float n1a = x1a * ca - x2a * sa;
    const float n2a = x1a * sa + x2a * ca;
    const float n1b = x1b * cb - x2b * sb2;
    const float n2b = x1b * sb2 + x2b * cb;

    float sq = n1a * n1a + n2a * n2a + n1b * n1b + n2b * n2b;
#pragma unroll
    for (int o = 16; o > 0; o >>= 1)
        sq += __shfl_xor_sync(0xffffffffu, sq, o);

    const float rs = rsqrtf(sq * (1.0f / 128.0f) + RMS_EPS);

    __half* dst = sel ? kh : qh;
    dst[base + lane]      = __float2half_rn(n1a * rs);
    dst[base + 32 + lane] = __float2half_rn(n1b * rs);
    dst[base + 64 + lane] = __float2half_rn(n2a * rs);
    dst[base + 96 + lane] = __float2half_rn(n2b * rs);
}

// =====================================================================
// Flash attention, fp16 mma: S = 1 chain (Q,K single),
// P·V = 1 chain. Q fragments in registers. Output fp16 single.
// smem: [0, 2*FL_TILE) = Q; then 2 KV stages (K tile + V tile).
// =====================================================================
#define FL_STR  136
#define FL_ROWB (FL_STR*2)
#define FL_TILE (64*FL_ROWB)            // 17408
#define FL_STG  (2*FL_TILE)             // 34816
#define FL_KV0  (2*FL_TILE)             // 34816 (after Q)
#define FL_SMEM (2*FL_TILE + 2*FL_STG)  // 104448

__global__ __launch_bounds__(256, 1) void flash_mma_kernel(
    const __half* __restrict__ Qh,
    const __half* __restrict__ Kh, const __half* __restrict__ Vh,
    __half* __restrict__ Y)
{
    extern __shared__ char smc[];
    const uint32_t sb = smem_to_u32(smc);
    const int t = threadIdx.x;
    const int lane = t & 31;
    const int w = t >> 5;
    const int qi = gridDim.x - 1 - blockIdx.x;
    const int h = blockIdx.y, b = blockIdx.z;
    const int qs = qi * 128;
    const size_t hb = ((size_t)b * SEQ) * EMB + (size_t)h * HDIM;

#pragma unroll
    for (int i = 0; i < 8; i++) {
        const int idx = t + i * 256;
        const int r = idx >> 4, c = idx & 15;
        CP_ASYNC16(sb + r * FL_ROWB + c * 16,
                   Qh + hb + (size_t)(qs + r) * EMB + c * 8);
    }
    CP_COMMIT();

    auto load_kv = [&](int s, int ks) {
        const uint32_t base = sb + FL_KV0 + s * FL_STG;
#pragma unroll
        for (int i = 0; i < 4; i++) {
            const int idx = t + i * 256;
            const int r = idx >> 4, c = idx & 15;
            const size_t g = hb + (size_t)(ks + r) * EMB + c * 8;
            CP_ASYNC16(base + r * FL_ROWB + c * 16, Kh + g);
            CP_ASYNC16(base + FL_TILE + r * FL_ROWB + c * 16, Vh + g);
        }
    };

    load_kv(0, 0);
    CP_COMMIT();

    float m0 = -INFINITY, m1 = -INFINITY, l0 = 0.f, l1 = 0.f;
    float o[16][4];
#pragma unroll
    for (int i = 0; i < 16; i++)
#pragma unroll
        for (int j = 0; j < 4; j++) o[i][j] = 0.f;

    const uint32_t q_addr = sb + (w * 16 + (lane & 15)) * FL_ROWB + (lane >> 4) * 16;
    const int krow = (lane & 7) + ((lane >> 4) << 3);
    const uint32_t kcolb = ((lane >> 3) & 1) * 16;
    const int vrow = (lane & 7) + (((lane >> 3) & 1) << 3);
    const uint32_t vcolb = (lane >> 4) * 16;

    const int r0g = qs + w * 16 + (lane >> 2);
    const int r1g = r0g + 8;
    const int nkt = (qs + 128) / 64;

    CP_WAIT0();
    __syncthreads();
    uint32_t qa_r[8][4];
#pragma unroll
    for (int kf = 0; kf < 8; kf++)
        ldsm4(qa_r[kf], q_addr + kf * 32);

    for (int jt = 0; jt < nkt; jt++) {
        CP_WAIT0();
        __syncthreads();
        if (jt + 1 < nkt) { load_kv((jt + 1) & 1, (jt + 1) * 64); CP_COMMIT(); }

        const int ks = jt * 64;
        if (ks <= qs + w * 16 + 15) {
            const uint32_t kb = sb + FL_KV0 + (jt & 1) * FL_STG;

            float s[8][4];
#pragma unroll
            for (int i = 0; i < 8; i++)
#pragma unroll
                for (int j = 0; j < 4; j++) s[i][j] = 0.f;

#pragma unroll
            for (int kf = 0; kf < 8; kf++) {
#pragma unroll
                for (int nfp = 0; nfp < 4; nfp++) {
                    uint32_t kh4[4];
                    ldsm4(kh4, kb + (nfp * 16 + krow) * FL_ROWB + kcolb + kf * 32);
                    mma_f16(s[2 * nfp], qa_r[kf], kh4);
                    mma_f16(s[2 * nfp + 1], qa_r[kf], kh4 + 2);
                }
            }

            if (ks + 63 > r0g) {
#pragma unroll
                for (int nf = 0; nf < 8; nf++) {
                    const int kc = ks + nf * 8 + (lane & 3) * 2;
                    if (kc > r0g)     s[nf][0] = -1e30f;
                    if (kc + 1 > r0g) s[nf][1] = -1e30f;
                    if (kc > r1g)     s[nf][2] = -1e30f;
                    if (kc + 1 > r1g) s[nf][3] = -1e30f;
                }
            }

            float m0l = -INFINITY, m1l = -INFINITY;
#pragma unroll
            for (int nf = 0; nf < 8; nf++) {
                m0l = fmaxf(m0l, fmaxf(s[nf][0], s[nf][1]));
                m1l = fmaxf(m1l, fmaxf(s[nf][2], s[nf][3]));
            }
            m0l = fmaxf(m0l, __shfl_xor_sync(0xffffffffu, m0l, 1));
            m0l = fmaxf(m0l, __shfl_xor_sync(0xffffffffu, m0l, 2));
            m1l = fmaxf(m1l, __shfl_xor_sync(0xffffffffu, m1l, 1));
            m1l = fmaxf(m1l, __shfl_xor_sync(0xffffffffu, m1l, 2));
            const float m0n = fmaxf(m0, m0l), m1n = fmaxf(m1, m1l);
            const float a0 = ex2((m0 - m0n) * SL2E);
            const float a1 = ex2((m1 - m1n) * SL2E);
            m0 = m0n; m1 = m1n;

            float sum0 = 0.f, sum1 = 0.f;
#pragma unroll
            for (int nf = 0; nf < 8; nf++) {
                s[nf][0] = ex2((s[nf][0] - m0n) * SL2E); sum0 += s[nf][0];
                s[nf][1] = ex2((s[nf][1] - m0n) * SL2E); sum0 += s[nf][1];
                s[nf][2] = ex2((s[nf][2] - m1n) * SL2E); sum1 += s[nf][2];
                s[nf][3] = ex2((s[nf][3] - m1n) * SL2E); sum1 += s[nf][3];
            }
            sum0 += __shfl_xor_sync(0xffffffffu, sum0, 1);
            sum0 += __shfl_xor_sync(0xffffffffu, sum0, 2);
            sum1 += __shfl_xor_sync(0xffffffffu, sum1, 1);
            sum1 += __shfl_xor_sync(0xffffffffu, sum1, 2);
            l0 = l0 * a0 + sum0;
            l1 = l1 * a1 + sum1;

#pragma unroll
            for (int nf = 0; nf < 16; nf++) {
                o[nf][0] *= a0; o[nf][1] *= a0;
                o[nf][2] *= a1; o[nf][3] *= a1;
            }

            const uint32_t vb = kb + FL_TILE;
#pragma unroll
            for (int kf2 = 0; kf2 < 4; kf2++) {
                uint32_t ah[4];
#pragma unroll
                for (int q2 = 0; q2 < 2; q2++) {
                    const float* sp = s[2 * kf2 + q2];
                    ah[q2 * 2 + 0] = pack_f16x2(sp[0], sp[1]);
                    ah[q2 * 2 + 1] = pack_f16x2(sp[2], sp[3]);
                }
#pragma unroll
                for (int nfp = 0; nfp < 8; nfp++) {
                    uint32_t vh4[4];
                    ldsm4t(vh4, vb + (kf2 * 16 + vrow) * FL_ROWB + vcolb + nfp * 32);
                    mma_f16(o[2 * nfp], ah, vh4);
                    mma_f16(o[2 * nfp + 1], ah, vh4 + 2);
                }
            }
        }
    }

    const float il0 = 1.f / l0, il1 = 1.f / l1;
    const size_t yb = hb + (size_t)r0g * EMB + (lane & 3) * 2;
#pragma unroll
    for (int nf = 0; nf < 16; nf++) {
        *(uint32_t*)(Y + yb + nf * 8) =
            pack_f16x2(o[nf][0] * il0, o[nf][1] * il0);
        *(uint32_t*)(Y + yb + (size_t)8 * EMB + nf * 8) =
            pack_f16x2(o[nf][2] * il1, o[nf][3] * il1);
    }
}

// =====================================================================
// launch
// =====================================================================
extern "C" void kernel_launch(void* const* d_in, const int* in_sizes, int n_in,
                              void* d_out, int out_size)
{
    const float* x  = (const float*)d_in[0];
    const float* wq = (const float*)d_in[1];
    const float* wk = (const float*)d_in[2];
    const float* wv = (const float*)d_in[3];
    const float* wo = (const float*)d_in[4];
    float* out = (float*)d_out;

    float *gq, *gk, *ct, *st;
    __half *ga, *wthi, *qh, *kh, *vh;
    cudaGetSymbolAddress((void**)&gq, g_q);
    cudaGetSymbolAddress((void**)&gk, g_k);
    cudaGetSymbolAddress((void**)&ct, g_cos);
    cudaGetSymbolAddress((void**)&st, g_sin);
    cudaGetSymbolAddress((void**)&ga, g_a);
    cudaGetSymbolAddress((void**)&wthi, g_wthi);
    cudaGetSymbolAddress((void**)&qh, g_qh);
    cudaGetSymbolAddress((void**)&kh, g_kh);
    cudaGetSymbolAddress((void**)&vh, g_vh);

    cudaFuncSetAttribute(mma_gemm_kernel,
                         cudaFuncAttributeMaxDynamicSharedMemorySize, GEMM_SMEM);
    cudaFuncSetAttribute(flash_mma_kernel,
                         cudaFuncAttributeMaxDynamicSharedMemorySize, FL_SMEM);

    const int n4 = (int)(ELEMS / 4);
    const dim3 sgrid((n4 + 255) / 256);
    const size_t WSZ = (size_t)EMB * EMB;

    // prep: rope tables, x -> fp16, all 4 weights (x64, fp16) in one launch
    rope_table_kernel<<<(SEQ * 64 + 255) / 256, 256>>>(ct, st);
    conv16_kernel<<<sgrid, 256>>>(x, ga, n4);
    dim3 wgrid(EMB / 32, EMB / 32, 4);
    wsplit4_kernel<<<wgrid, 256>>>(wq, wk, wv, wo, wthi);

    // fused QKV GEMM: q,k fp32; v directly fp16 single
    dim3 qkvgrid(3 * EMB / BN, MROWS / BM);   // (24, 64)
    mma_gemm_kernel<<<qkvgrid, 256, GEMM_SMEM>>>(
        ga, wthi, EMB, 1, gq, gk, vh);

    // RoPE + RMSNorm: Q, K -> fp16 single
    ropeprep2_kernel<<<2 * BATCH * SEQ * NHEAD / 8, 256>>>(
        gq, gk, ct, st, qh, kh);

    // flash attention -> writes ga (fp16 single) directly
    dim3 fgrid(SEQ / 128, NHEAD, BATCH);
    flash_mma_kernel<<<fgrid, 256, FL_SMEM>>>(qh, kh, vh, ga);

    // out = y @ wo
    dim3 ogrid(EMB / BN, MROWS / BM);
    mma_gemm_kernel<<<ogrid, 256, GEMM_SMEM>>>(
        ga, wthi + 3 * WSZ, EMB, 0, out, nullptr, nullptr);
}